// round 11
// baseline (speedup 1.0000x reference)
#include <cuda_runtime.h>
#include <math.h>

// Problem constants (shapes fixed by the dataset)
#define NN   50000
#define EE   800000
#define DIN  64
#define DOUT 128

// Scratch (no cudaMalloc allowed)
__device__ int   g_is64;
__device__ int   g_degi[NN];            // incoming-edge count (no self-loop)
__device__ int   g_start[NN + 1];       // CSR offsets by dst
__device__ int   g_cursor[NN];          // fill cursors
__device__ float g_dinv[NN];
__device__ int2  g_edge[EE];            // (src, __float_as_int(norm)) sorted by dst
__device__ __align__(128) float g_aggx[(size_t)NN * DIN];

// ---------------------------------------------------------------------------
// K0: detect edge_index dtype. If int64, upper 32-bit words of the first 16
// entries are all zero (indices < 2^31). If int32, those words are 16
// independent random indices in [0, 50000) — all-zero has probability ~0.
__global__ void k_detect(const int* __restrict__ ei) {
    int is64 = 1;
    #pragma unroll
    for (int k = 0; k < 16; k++)
        if (ei[2 * k + 1] != 0) is64 = 0;
    g_is64 = is64;
}

__device__ __forceinline__ int edge_at(const int* __restrict__ ei, int i, int is64) {
    return is64 ? (int)((const long long*)ei)[i] : ei[i];
}

// K1: zero degree histogram
__global__ void k_zero(int N) {
    int i = blockIdx.x * blockDim.x + threadIdx.x;
    if (i < N) g_degi[i] = 0;
}

// K2: degi[dst] += 1 per edge (guarded: invalid dst never counted)
__global__ void k_count(const int* __restrict__ ei, int E, int N) {
    const int is64 = g_is64;
    int e = blockIdx.x * blockDim.x + threadIdx.x;
    if (e < E) {
        int d = edge_at(ei, E + e, is64);
        if ((unsigned)d < (unsigned)N)
            atomicAdd(&g_degi[d], 1);
    }
}

// K3: exclusive scan of degi -> g_start; zero cursors. Single block.
__global__ void k_scan(int N) {
    __shared__ int ssum[1024];
    const int t = threadIdx.x;
    const int chunk = (N + 1023) / 1024;
    const int lo = t * chunk;
    const int hi = min(lo + chunk, N);

    int sum = 0;
    for (int i = lo; i < hi; i++) sum += g_degi[i];
    ssum[t] = sum;
    __syncthreads();
    for (int off = 1; off < 1024; off <<= 1) {
        int v = (t >= off) ? ssum[t - off] : 0;
        __syncthreads();
        ssum[t] += v;
        __syncthreads();
    }
    int run = (t == 0) ? 0 : ssum[t - 1];
    for (int i = lo; i < hi; i++) {
        g_start[i]  = run;
        g_cursor[i] = 0;
        run += g_degi[i];
    }
    if (t == 1023) g_start[N] = run;
}

// K4: dinv = rsqrt(deg_in + 1)   (+1 = self-loop; always >= 1)
__global__ void k_dinv(int N) {
    int i = blockIdx.x * blockDim.x + threadIdx.x;
    if (i < N) g_dinv[i] = rsqrtf((float)(g_degi[i] + 1));
}

// K5: reorder edges into CSR-by-dst with packed (src, norm).
// Invariant: every edge counted in k_count gets exactly one slot written
// (invalid src -> norm 0), so gather never reads garbage.
__global__ void k_reorder(const int* __restrict__ ei, int E, int N) {
    const int is64 = g_is64;
    int e = blockIdx.x * blockDim.x + threadIdx.x;
    if (e >= E) return;
    int d = edge_at(ei, E + e, is64);
    if ((unsigned)d >= (unsigned)N) return;            // never counted -> skip
    int s = edge_at(ei, e, is64);
    float nrm = 0.0f;
    if ((unsigned)s < (unsigned)N) {
        nrm = g_dinv[s] * g_dinv[d];
    } else {
        s = 0;                                         // slot written, contributes 0
    }
    int pos = g_start[d] + atomicAdd(&g_cursor[d], 1);
    g_edge[pos] = make_int2(s, __float_as_int(nrm));
}

// K6: gather  aggx[n] = x[n]*dinv[n]^2 + sum_{e: dst=e} x[src_e]*norm_e
// One warp per node; lane holds float2 (2 of 64 columns). No atomics.
__global__ void k_gather(const float2* __restrict__ x2, int N) {
    int w = (blockIdx.x * blockDim.x + threadIdx.x) >> 5;
    if (w >= N) return;
    int lane = threadIdx.x & 31;

    float di = g_dinv[w];
    float sc = di * di;
    float2 acc = x2[(size_t)w * 32 + lane];
    acc.x *= sc; acc.y *= sc;

    int i   = g_start[w];
    int end = g_start[w + 1];
    for (; i + 1 < end; i += 2) {                      // 2-edge unroll (MLP)
        int2 e0 = g_edge[i];
        int2 e1 = g_edge[i + 1];
        float n0 = __int_as_float(e0.y);
        float n1 = __int_as_float(e1.y);
        float2 v0 = x2[(size_t)e0.x * 32 + lane];
        float2 v1 = x2[(size_t)e1.x * 32 + lane];
        acc.x += v0.x * n0 + v1.x * n1;
        acc.y += v0.y * n0 + v1.y * n1;
    }
    if (i < end) {
        int2 e0 = g_edge[i];
        float n0 = __int_as_float(e0.y);
        float2 v0 = x2[(size_t)e0.x * 32 + lane];
        acc.x += v0.x * n0;
        acc.y += v0.y * n0;
    }
    ((float2*)g_aggx)[(size_t)w * 32 + lane] = acc;
}

// ---------------------------------------------------------------------------
// K7: fused  out = SiLU( LN(aggx@W + b)*ln_w + ln_b + x@res_W + res_b )
// Block = 256 threads = 8 warps. Tile = 32 nodes. Each thread: 4 nodes x 4 cols
// for BOTH GEMMs (32 accumulators). W/res_W staged in shared (64 KB),
// aggx/x tiles staged per block (16 KB). LayerNorm via warp shuffles (each
// warp owns 4 whole nodes: lanes 0..31 cover all 128 columns).
__global__ void k_fused(const float* __restrict__ x,
                        const float* __restrict__ W,
                        const float* __restrict__ b,
                        const float* __restrict__ lnw,
                        const float* __restrict__ lnb,
                        const float* __restrict__ Rw,
                        const float* __restrict__ rb,
                        float* __restrict__ out, int N) {
    extern __shared__ float sh[];
    float* Wsh = sh;                 // 64*128 = 8192 floats
    float* Rsh = sh + 8192;          // 8192
    float* Ash = sh + 16384;         // 32*64 = 2048
    float* Xsh = sh + 18432;         // 2048

    const int tid = threadIdx.x;
    const int m0  = blockIdx.x * 32;

    // Stage weights (2048 float4 each)
    {
        float4* Wd = (float4*)Wsh; const float4* Wg = (const float4*)W;
        float4* Rd = (float4*)Rsh; const float4* Rg = (const float4*)Rw;
        #pragma unroll
        for (int i = 0; i < 8; i++) {
            Wd[tid + i * 256] = Wg[tid + i * 256];
            Rd[tid + i * 256] = Rg[tid + i * 256];
        }
    }
    // Stage node tiles: 512 float4 each (2 per thread)
    {
        float4* Ad = (float4*)Ash; const float4* Ag = (const float4*)g_aggx;
        float4* Xd = (float4*)Xsh; const float4* Xg = (const float4*)x;
        #pragma unroll
        for (int i = 0; i < 2; i++) {
            int idx  = tid + i * 256;          // 0..511
            int node = m0 + (idx >> 4);
            int c    = idx & 15;
            float4 av = make_float4(0.f, 0.f, 0.f, 0.f);
            float4 xv = make_float4(0.f, 0.f, 0.f, 0.f);
            if (node < N) {
                av = Ag[(size_t)node * 16 + c];
                xv = Xg[(size_t)node * 16 + c];
            }
            Ad[idx] = av;
            Xd[idx] = xv;
        }
    }
    __syncthreads();

    const int my = tid >> 5;   // warp id 0..7  -> nodes my, my+8, my+16, my+24
    const int cx = tid & 31;   // lane -> columns cx*4 .. cx*4+3

    float4 accA[4] = {};
    float4 accR[4] = {};

    #pragma unroll 16
    for (int k = 0; k < DIN; k++) {
        float4 wv = *(const float4*)&Wsh[k * DOUT + cx * 4];
        float4 rv = *(const float4*)&Rsh[k * DOUT + cx * 4];
        #pragma unroll
        for (int nn = 0; nn < 4; nn++) {
            float a  = Ash[(my + 8 * nn) * DIN + k];
            float xx = Xsh[(my + 8 * nn) * DIN + k];
            accA[nn].x += wv.x * a;  accA[nn].y += wv.y * a;
            accA[nn].z += wv.z * a;  accA[nn].w += wv.w * a;
            accR[nn].x += rv.x * xx; accR[nn].y += rv.y * xx;
            accR[nn].z += rv.z * xx; accR[nn].w += rv.w * xx;
        }
    }

    const float4 bv  = ((const float4*)b)[cx];
    const float4 lw  = ((const float4*)lnw)[cx];
    const float4 lb  = ((const float4*)lnb)[cx];
    const float4 rbv = ((const float4*)rb)[cx];

    #pragma unroll
    for (int nn = 0; nn < 4; nn++) {
        float4 a = accA[nn];
        a.x += bv.x; a.y += bv.y; a.z += bv.z; a.w += bv.w;

        float s = a.x + a.y + a.z + a.w;
        float q = a.x * a.x + a.y * a.y + a.z * a.z + a.w * a.w;
        #pragma unroll
        for (int o = 16; o > 0; o >>= 1) {
            s += __shfl_xor_sync(0xffffffffu, s, o);
            q += __shfl_xor_sync(0xffffffffu, q, o);
        }
        float mu  = s * (1.0f / 128.0f);
        float var = q * (1.0f / 128.0f) - mu * mu;
        float inv = rsqrtf(var + 1e-5f);

        int node = m0 + my + 8 * nn;
        if (node < N) {
            float4 r = accR[nn];
            float4 o4;
            float h, y;
            h = (a.x - mu) * inv * lw.x + lb.x; y = h + r.x + rbv.x;
            o4.x = y * (1.0f / (1.0f + __expf(-y)));
            h = (a.y - mu) * inv * lw.y + lb.y; y = h + r.y + rbv.y;
            o4.y = y * (1.0f / (1.0f + __expf(-y)));
            h = (a.z - mu) * inv * lw.z + lb.z; y = h + r.z + rbv.z;
            o4.z = y * (1.0f / (1.0f + __expf(-y)));
            h = (a.w - mu) * inv * lw.w + lb.w; y = h + r.w + rbv.w;
            o4.w = y * (1.0f / (1.0f + __expf(-y)));
            ((float4*)out)[(size_t)node * 32 + cx] = o4;
        }
    }
}

// ---------------------------------------------------------------------------
extern "C" void kernel_launch(void* const* d_in, const int* in_sizes, int n_in,
                              void* d_out, int out_size) {
    const float* x   = (const float*)d_in[0];
    const int*   ei  = (const int*)d_in[1];     // int32 OR int64 (auto-detected)
    const float* W   = (const float*)d_in[2];
    const float* b   = (const float*)d_in[3];
    const float* lnw = (const float*)d_in[4];
    const float* lnb = (const float*)d_in[5];
    const float* Rw  = (const float*)d_in[6];
    const float* rb  = (const float*)d_in[7];
    float*       out = (float*)d_out;

    const int N = in_sizes[0] / DIN;       // 50000
    const int E = in_sizes[1] / 2;         // 800000

    const size_t SMEM5 = (8192 + 8192 + 2048 + 2048) * sizeof(float); // 80 KB
    cudaFuncSetAttribute(k_fused, cudaFuncAttributeMaxDynamicSharedMemorySize,
                         (int)SMEM5);

    k_detect<<<1, 1>>>(ei);
    k_zero<<<(N + 255) / 256, 256>>>(N);
    k_count<<<(E + 255) / 256, 256>>>(ei, E, N);
    k_scan<<<1, 1024>>>(N);
    k_dinv<<<(N + 255) / 256, 256>>>(N);
    k_reorder<<<(E + 255) / 256, 256>>>(ei, E, N);
    {
        int warps  = N;                       // one warp per node
        int blocks = (warps * 32 + 255) / 256;
        k_gather<<<blocks, 256>>>((const float2*)x, N);
    }
    k_fused<<<(N + 31) / 32, 256, SMEM5>>>(x, W, b, lnw, lnb, Rw, rb, out, N);
}

// round 12
// speedup vs baseline: 1.6279x; 1.6279x over previous
#include <cuda_runtime.h>
#include <math.h>

// Problem constants (shapes fixed by the dataset)
#define NN   50000
#define EE   800000
#define DIN  64
#define DOUT 128

// Scratch (no cudaMalloc allowed)
__device__ int   g_is64;
__device__ int   g_degi[NN];            // incoming-edge count (no self-loop)
__device__ int   g_start[NN + 1];       // CSR offsets by dst
__device__ int   g_cursor[NN];          // fill cursors
__device__ float g_dinv[NN];
__device__ int   g_bsum[256];           // per-block degree sums (196 used)
__device__ int   g_boff[256];           // exclusive scan of block sums
__device__ int   g_total;               // total counted edges
__device__ int2  g_edge[EE];            // (src, __float_as_int(norm)) sorted by dst
__device__ __align__(128) float g_aggx[(size_t)NN * DIN];

// ---------------------------------------------------------------------------
// K0: detect edge_index dtype. If int64, upper 32-bit words of the first 16
// entries are all zero (indices < 2^31). If int32, those words are 16
// independent random indices in [0, 50000) — all-zero has probability ~0.
__global__ void k_detect(const int* __restrict__ ei) {
    int is64 = 1;
    #pragma unroll
    for (int k = 0; k < 16; k++)
        if (ei[2 * k + 1] != 0) is64 = 0;
    g_is64 = is64;
}

__device__ __forceinline__ int edge_at(const int* __restrict__ ei, int i, int is64) {
    return is64 ? (int)((const long long*)ei)[i] : ei[i];
}

// K1: zero degree histogram
__global__ void k_zero(int N) {
    int i = blockIdx.x * blockDim.x + threadIdx.x;
    if (i < N) g_degi[i] = 0;
}

// K2: degi[dst] += 1 per edge (guarded: invalid dst never counted)
__global__ void k_count(const int* __restrict__ ei, int E, int N) {
    const int is64 = g_is64;
    int e = blockIdx.x * blockDim.x + threadIdx.x;
    if (e < E) {
        int d = edge_at(ei, E + e, is64);
        if ((unsigned)d < (unsigned)N)
            atomicAdd(&g_degi[d], 1);
    }
}

// K3a: per-block scan (256 elems/block). Writes within-block exclusive prefix
// to g_start and the block total to g_bsum.
__global__ void k_scanA(int N) {
    __shared__ int sh[256];
    const int t = threadIdx.x;
    const int i = blockIdx.x * 256 + t;
    int v = (i < N) ? g_degi[i] : 0;
    sh[t] = v;
    __syncthreads();
    #pragma unroll
    for (int off = 1; off < 256; off <<= 1) {
        int u = (t >= off) ? sh[t - off] : 0;
        __syncthreads();
        sh[t] += u;
        __syncthreads();
    }
    if (i < N) g_start[i] = sh[t] - v;             // exclusive within block
    if (t == 255) g_bsum[blockIdx.x] = sh[255];
}

// K3b: exclusive scan of block sums (nblk <= 256). Single tiny block.
__global__ void k_scanB(int nblk) {
    __shared__ int sh[256];
    const int t = threadIdx.x;
    int v = (t < nblk) ? g_bsum[t] : 0;
    sh[t] = v;
    __syncthreads();
    #pragma unroll
    for (int off = 1; off < 256; off <<= 1) {
        int u = (t >= off) ? sh[t - off] : 0;
        __syncthreads();
        sh[t] += u;
        __syncthreads();
    }
    if (t < nblk) g_boff[t] = sh[t] - v;           // exclusive
    if (t == 255) g_total = sh[255];
}

// K3c: apply block offsets; zero cursors; dinv = rsqrt(deg+1); g_start[N].
__global__ void k_scanC(int N) {
    int i = blockIdx.x * blockDim.x + threadIdx.x;
    if (i < N) {
        g_start[i] += g_boff[i >> 8];
        g_cursor[i] = 0;
        g_dinv[i]   = rsqrtf((float)(g_degi[i] + 1));
    }
    if (i == 0) g_start[N] = g_total;
}

// K5: reorder edges into CSR-by-dst with packed (src, norm).
// Invariant: every edge counted in k_count gets exactly one slot written
// (invalid src -> norm 0), so gather never reads garbage.
__global__ void k_reorder(const int* __restrict__ ei, int E, int N) {
    const int is64 = g_is64;
    int e = blockIdx.x * blockDim.x + threadIdx.x;
    if (e >= E) return;
    int d = edge_at(ei, E + e, is64);
    if ((unsigned)d >= (unsigned)N) return;            // never counted -> skip
    int s = edge_at(ei, e, is64);
    float nrm = 0.0f;
    if ((unsigned)s < (unsigned)N) {
        nrm = g_dinv[s] * g_dinv[d];
    } else {
        s = 0;                                         // slot written, contributes 0
    }
    int pos = g_start[d] + atomicAdd(&g_cursor[d], 1);
    g_edge[pos] = make_int2(s, __float_as_int(nrm));
}

// K6: gather  aggx[n] = x[n]*dinv[n]^2 + sum_{e: dst=e} x[src_e]*norm_e
// One warp per node; lane holds float2 (2 of 64 columns). No atomics.
__global__ void k_gather(const float2* __restrict__ x2, int N) {
    int w = (blockIdx.x * blockDim.x + threadIdx.x) >> 5;
    if (w >= N) return;
    int lane = threadIdx.x & 31;

    float di = g_dinv[w];
    float sc = di * di;
    float2 acc = x2[(size_t)w * 32 + lane];
    acc.x *= sc; acc.y *= sc;

    int i   = g_start[w];
    int end = g_start[w + 1];
    for (; i + 1 < end; i += 2) {                      // 2-edge unroll (MLP)
        int2 e0 = g_edge[i];
        int2 e1 = g_edge[i + 1];
        float n0 = __int_as_float(e0.y);
        float n1 = __int_as_float(e1.y);
        float2 v0 = x2[(size_t)e0.x * 32 + lane];
        float2 v1 = x2[(size_t)e1.x * 32 + lane];
        acc.x += v0.x * n0 + v1.x * n1;
        acc.y += v0.y * n0 + v1.y * n1;
    }
    if (i < end) {
        int2 e0 = g_edge[i];
        float n0 = __int_as_float(e0.y);
        float2 v0 = x2[(size_t)e0.x * 32 + lane];
        acc.x += v0.x * n0;
        acc.y += v0.y * n0;
    }
    ((float2*)g_aggx)[(size_t)w * 32 + lane] = acc;
}

// ---------------------------------------------------------------------------
// K7: fused  out = SiLU( LN(aggx@W + b)*ln_w + ln_b + x@res_W + res_b )
// Block = 256 threads = 8 warps. Tile = 32 nodes. Each thread: 4 nodes x 4 cols
// for BOTH GEMMs (32 accumulators). W/res_W staged in shared (64 KB),
// aggx/x tiles staged per block (16 KB). LayerNorm via warp shuffles (each
// warp owns 4 whole nodes: lanes 0..31 cover all 128 columns).
__global__ void k_fused(const float* __restrict__ x,
                        const float* __restrict__ W,
                        const float* __restrict__ b,
                        const float* __restrict__ lnw,
                        const float* __restrict__ lnb,
                        const float* __restrict__ Rw,
                        const float* __restrict__ rb,
                        float* __restrict__ out, int N) {
    extern __shared__ float sh[];
    float* Wsh = sh;                 // 64*128 = 8192 floats
    float* Rsh = sh + 8192;          // 8192
    float* Ash = sh + 16384;         // 32*64 = 2048
    float* Xsh = sh + 18432;         // 2048

    const int tid = threadIdx.x;
    const int m0  = blockIdx.x * 32;

    // Stage weights (2048 float4 each)
    {
        float4* Wd = (float4*)Wsh; const float4* Wg = (const float4*)W;
        float4* Rd = (float4*)Rsh; const float4* Rg = (const float4*)Rw;
        #pragma unroll
        for (int i = 0; i < 8; i++) {
            Wd[tid + i * 256] = Wg[tid + i * 256];
            Rd[tid + i * 256] = Rg[tid + i * 256];
        }
    }
    // Stage node tiles: 512 float4 each (2 per thread)
    {
        float4* Ad = (float4*)Ash; const float4* Ag = (const float4*)g_aggx;
        float4* Xd = (float4*)Xsh; const float4* Xg = (const float4*)x;
        #pragma unroll
        for (int i = 0; i < 2; i++) {
            int idx  = tid + i * 256;          // 0..511
            int node = m0 + (idx >> 4);
            int c    = idx & 15;
            float4 av = make_float4(0.f, 0.f, 0.f, 0.f);
            float4 xv = make_float4(0.f, 0.f, 0.f, 0.f);
            if (node < N) {
                av = Ag[(size_t)node * 16 + c];
                xv = Xg[(size_t)node * 16 + c];
            }
            Ad[idx] = av;
            Xd[idx] = xv;
        }
    }
    __syncthreads();

    const int my = tid >> 5;   // warp id 0..7  -> nodes my, my+8, my+16, my+24
    const int cx = tid & 31;   // lane -> columns cx*4 .. cx*4+3

    float4 accA[4] = {};
    float4 accR[4] = {};

    #pragma unroll 16
    for (int k = 0; k < DIN; k++) {
        float4 wv = *(const float4*)&Wsh[k * DOUT + cx * 4];
        float4 rv = *(const float4*)&Rsh[k * DOUT + cx * 4];
        #pragma unroll
        for (int nn = 0; nn < 4; nn++) {
            float a  = Ash[(my + 8 * nn) * DIN + k];
            float xx = Xsh[(my + 8 * nn) * DIN + k];
            accA[nn].x += wv.x * a;  accA[nn].y += wv.y * a;
            accA[nn].z += wv.z * a;  accA[nn].w += wv.w * a;
            accR[nn].x += rv.x * xx; accR[nn].y += rv.y * xx;
            accR[nn].z += rv.z * xx; accR[nn].w += rv.w * xx;
        }
    }

    const float4 bv  = ((const float4*)b)[cx];
    const float4 lw  = ((const float4*)lnw)[cx];
    const float4 lb  = ((const float4*)lnb)[cx];
    const float4 rbv = ((const float4*)rb)[cx];

    #pragma unroll
    for (int nn = 0; nn < 4; nn++) {
        float4 a = accA[nn];
        a.x += bv.x; a.y += bv.y; a.z += bv.z; a.w += bv.w;

        float s = a.x + a.y + a.z + a.w;
        float q = a.x * a.x + a.y * a.y + a.z * a.z + a.w * a.w;
        #pragma unroll
        for (int o = 16; o > 0; o >>= 1) {
            s += __shfl_xor_sync(0xffffffffu, s, o);
            q += __shfl_xor_sync(0xffffffffu, q, o);
        }
        float mu  = s * (1.0f / 128.0f);
        float var = q * (1.0f / 128.0f) - mu * mu;
        float inv = rsqrtf(var + 1e-5f);

        int node = m0 + my + 8 * nn;
        if (node < N) {
            float4 r = accR[nn];
            float4 o4;
            float h, y;
            h = (a.x - mu) * inv * lw.x + lb.x; y = h + r.x + rbv.x;
            o4.x = y * (1.0f / (1.0f + __expf(-y)));
            h = (a.y - mu) * inv * lw.y + lb.y; y = h + r.y + rbv.y;
            o4.y = y * (1.0f / (1.0f + __expf(-y)));
            h = (a.z - mu) * inv * lw.z + lb.z; y = h + r.z + rbv.z;
            o4.z = y * (1.0f / (1.0f + __expf(-y)));
            h = (a.w - mu) * inv * lw.w + lb.w; y = h + r.w + rbv.w;
            o4.w = y * (1.0f / (1.0f + __expf(-y)));
            ((float4*)out)[(size_t)node * 32 + cx] = o4;
        }
    }
}

// ---------------------------------------------------------------------------
extern "C" void kernel_launch(void* const* d_in, const int* in_sizes, int n_in,
                              void* d_out, int out_size) {
    const float* x   = (const float*)d_in[0];
    const int*   ei  = (const int*)d_in[1];     // int32 OR int64 (auto-detected)
    const float* W   = (const float*)d_in[2];
    const float* b   = (const float*)d_in[3];
    const float* lnw = (const float*)d_in[4];
    const float* lnb = (const float*)d_in[5];
    const float* Rw  = (const float*)d_in[6];
    const float* rb  = (const float*)d_in[7];
    float*       out = (float*)d_out;

    const int N = in_sizes[0] / DIN;       // 50000
    const int E = in_sizes[1] / 2;         // 800000

    const size_t SMEM5 = (8192 + 8192 + 2048 + 2048) * sizeof(float); // 80 KB
    cudaFuncSetAttribute(k_fused, cudaFuncAttributeMaxDynamicSharedMemorySize,
                         (int)SMEM5);

    const int nblk = (N + 255) / 256;      // 196 scan blocks

    k_detect<<<1, 1>>>(ei);
    k_zero<<<(N + 255) / 256, 256>>>(N);
    k_count<<<(E + 255) / 256, 256>>>(ei, E, N);
    k_scanA<<<nblk, 256>>>(N);
    k_scanB<<<1, 256>>>(nblk);
    k_scanC<<<(N + 255) / 256, 256>>>(N);
    k_reorder<<<(E + 255) / 256, 256>>>(ei, E, N);
    {
        int warps  = N;                       // one warp per node
        int blocks = (warps * 32 + 255) / 256;
        k_gather<<<blocks, 256>>>((const float2*)x, N);
    }
    k_fused<<<(N + 31) / 32, 256, SMEM5>>>(x, W, b, lnw, lnb, Rw, rb, out, N);
}

// round 13
// speedup vs baseline: 1.7446x; 1.0717x over previous
#include <cuda_runtime.h>
#include <math.h>
#include <string.h>

// Problem constants (shapes fixed by the dataset)
#define NN   50000
#define EE   800000
#define DIN  64
#define DOUT 128

// Scratch (no cudaMalloc allowed)
__device__ int   g_is64;
__device__ int   g_degi[NN];            // incoming-edge count (no self-loop)
__device__ int   g_start[NN + 1];       // CSR offsets by dst
__device__ int   g_cursor[NN];          // fill cursors
__device__ float g_dinv[NN];
__device__ int   g_bsum[256];           // per-block degree sums (196 used)
__device__ int   g_boff[256];           // exclusive scan of block sums
__device__ int   g_total;               // total counted edges
__device__ int2  g_edge[EE];            // (src, __float_as_int(norm)) sorted by dst
__device__ __align__(128) float g_aggx[(size_t)NN * DIN];

// Packed f32x2 FMA: d.lo += a.lo*b.lo; d.hi += a.hi*b.hi  (2x fp32 tput)
#define FMA2(d, a, b) \
    asm("fma.rn.f32x2 %0, %1, %2, %0;" : "+l"(d) : "l"(a), "l"(b))

__device__ __forceinline__ unsigned long long f2u(float lo, float hi) {
    float2 f = make_float2(lo, hi);
    unsigned long long u;
    memcpy(&u, &f, 8);
    return u;
}
__device__ __forceinline__ float2 u2f(unsigned long long u) {
    float2 f;
    memcpy(&f, &u, 8);
    return f;
}

__device__ __forceinline__ int edge_at(const int* __restrict__ ei, int i, int is64) {
    return is64 ? (int)((const long long*)ei)[i] : ei[i];
}

// ---------------------------------------------------------------------------
// K1: zero degree histogram + detect edge_index dtype (thread 0 of block 0).
// int64 detection: upper 32-bit words of first 16 entries all zero.
__global__ void k_zero(const int* __restrict__ ei, int N) {
    int i = blockIdx.x * blockDim.x + threadIdx.x;
    if (i < N) g_degi[i] = 0;
    if (i == 0) {
        int is64 = 1;
        #pragma unroll
        for (int k = 0; k < 16; k++)
            if (ei[2 * k + 1] != 0) is64 = 0;
        g_is64 = is64;
    }
}

// K2: degi[dst] += 1 per edge (guarded: invalid dst never counted)
__global__ void k_count(const int* __restrict__ ei, int E, int N) {
    const int is64 = g_is64;
    int e = blockIdx.x * blockDim.x + threadIdx.x;
    if (e < E) {
        int d = edge_at(ei, E + e, is64);
        if ((unsigned)d < (unsigned)N)
            atomicAdd(&g_degi[d], 1);
    }
}

// K3a: per-block scan (256 elems/block). Writes within-block exclusive prefix
// to g_start and the block total to g_bsum.
__global__ void k_scanA(int N) {
    __shared__ int sh[256];
    const int t = threadIdx.x;
    const int i = blockIdx.x * 256 + t;
    int v = (i < N) ? g_degi[i] : 0;
    sh[t] = v;
    __syncthreads();
    #pragma unroll
    for (int off = 1; off < 256; off <<= 1) {
        int u = (t >= off) ? sh[t - off] : 0;
        __syncthreads();
        sh[t] += u;
        __syncthreads();
    }
    if (i < N) g_start[i] = sh[t] - v;             // exclusive within block
    if (t == 255) g_bsum[blockIdx.x] = sh[255];
}

// K3b: exclusive scan of block sums (nblk <= 256). Single tiny block.
__global__ void k_scanB(int nblk) {
    __shared__ int sh[256];
    const int t = threadIdx.x;
    int v = (t < nblk) ? g_bsum[t] : 0;
    sh[t] = v;
    __syncthreads();
    #pragma unroll
    for (int off = 1; off < 256; off <<= 1) {
        int u = (t >= off) ? sh[t - off] : 0;
        __syncthreads();
        sh[t] += u;
        __syncthreads();
    }
    if (t < nblk) g_boff[t] = sh[t] - v;           // exclusive
    if (t == 255) g_total = sh[255];
}

// K3c: apply block offsets; zero cursors; dinv = rsqrt(deg+1); g_start[N].
__global__ void k_scanC(int N) {
    int i = blockIdx.x * blockDim.x + threadIdx.x;
    if (i < N) {
        g_start[i] += g_boff[i >> 8];
        g_cursor[i] = 0;
        g_dinv[i]   = rsqrtf((float)(g_degi[i] + 1));
    }
    if (i == 0) g_start[N] = g_total;
}

// K5: reorder edges into CSR-by-dst with packed (src, norm).
// Invariant: every edge counted in k_count gets exactly one slot written
// (invalid src -> norm 0), so gather never reads garbage.
__global__ void k_reorder(const int* __restrict__ ei, int E, int N) {
    const int is64 = g_is64;
    int e = blockIdx.x * blockDim.x + threadIdx.x;
    if (e >= E) return;
    int d = edge_at(ei, E + e, is64);
    if ((unsigned)d >= (unsigned)N) return;            // never counted -> skip
    int s = edge_at(ei, e, is64);
    float nrm = 0.0f;
    if ((unsigned)s < (unsigned)N) {
        nrm = g_dinv[s] * g_dinv[d];
    } else {
        s = 0;                                         // slot written, contributes 0
    }
    int pos = g_start[d] + atomicAdd(&g_cursor[d], 1);
    g_edge[pos] = make_int2(s, __float_as_int(nrm));
}

// K6: gather  aggx[n] = x[n]*dinv[n]^2 + sum_{e: dst=e} x[src_e]*norm_e
// One warp per node; lane holds float2 (2 of 64 columns). No atomics.
__global__ void k_gather(const float2* __restrict__ x2, int N) {
    int w = (blockIdx.x * blockDim.x + threadIdx.x) >> 5;
    if (w >= N) return;
    int lane = threadIdx.x & 31;

    float di = g_dinv[w];
    float sc = di * di;
    float2 acc = x2[(size_t)w * 32 + lane];
    acc.x *= sc; acc.y *= sc;

    int i   = g_start[w];
    int end = g_start[w + 1];
    for (; i + 1 < end; i += 2) {                      // 2-edge unroll (MLP)
        int2 e0 = g_edge[i];
        int2 e1 = g_edge[i + 1];
        float n0 = __int_as_float(e0.y);
        float n1 = __int_as_float(e1.y);
        float2 v0 = x2[(size_t)e0.x * 32 + lane];
        float2 v1 = x2[(size_t)e1.x * 32 + lane];
        acc.x += v0.x * n0 + v1.x * n1;
        acc.y += v0.y * n0 + v1.y * n1;
    }
    if (i < end) {
        int2 e0 = g_edge[i];
        float n0 = __int_as_float(e0.y);
        float2 v0 = x2[(size_t)e0.x * 32 + lane];
        acc.x += v0.x * n0;
        acc.y += v0.y * n0;
    }
    ((float2*)g_aggx)[(size_t)w * 32 + lane] = acc;
}

// ---------------------------------------------------------------------------
// K7: fused  out = SiLU( LN(aggx@W + b)*ln_w + ln_b + x@res_W + res_b )
// Block = 256 threads = 8 warps, 32-node tile. Inner loop uses packed
// fma.rn.f32x2 pairing over the K dimension: accumulator lanes hold
// (sum over even k, sum over odd k); halves added in the epilogue.
// Thread layout: warp my owns nodes my+8nn; lane owns cols lane+32j (j=0..3).
__global__ void k_fused(const float* __restrict__ x,
                        const float* __restrict__ W,
                        const float* __restrict__ b,
                        const float* __restrict__ lnw,
                        const float* __restrict__ lnb,
                        const float* __restrict__ Rw,
                        const float* __restrict__ rb,
                        float* __restrict__ out, int N) {
    extern __shared__ float sh[];
    float* Wsh = sh;                 // 64*128 = 8192 floats
    float* Rsh = sh + 8192;          // 8192
    float* Ash = sh + 16384;         // 32*64 = 2048
    float* Xsh = sh + 18432;         // 2048

    const int tid = threadIdx.x;
    const int m0  = blockIdx.x * 32;

    // Stage weights (2048 float4 each)
    {
        float4* Wd = (float4*)Wsh; const float4* Wg = (const float4*)W;
        float4* Rd = (float4*)Rsh; const float4* Rg = (const float4*)Rw;
        #pragma unroll
        for (int i = 0; i < 8; i++) {
            Wd[tid + i * 256] = Wg[tid + i * 256];
            Rd[tid + i * 256] = Rg[tid + i * 256];
        }
    }
    // Stage node tiles: 512 float4 each (2 per thread)
    {
        float4* Ad = (float4*)Ash; const float4* Ag = (const float4*)g_aggx;
        float4* Xd = (float4*)Xsh; const float4* Xg = (const float4*)x;
        #pragma unroll
        for (int i = 0; i < 2; i++) {
            int idx  = tid + i * 256;          // 0..511
            int node = m0 + (idx >> 4);
            int c    = idx & 15;
            float4 av = make_float4(0.f, 0.f, 0.f, 0.f);
            float4 xv = make_float4(0.f, 0.f, 0.f, 0.f);
            if (node < N) {
                av = Ag[(size_t)node * 16 + c];
                xv = Xg[(size_t)node * 16 + c];
            }
            Ad[idx] = av;
            Xd[idx] = xv;
        }
    }
    __syncthreads();

    const int my   = tid >> 5;   // warp id 0..7 -> nodes my, my+8, my+16, my+24
    const int lane = tid & 31;   // lane -> cols lane, lane+32, lane+64, lane+96

    unsigned long long accA2[4][4];   // [node][colgroup] packed (even-k, odd-k)
    unsigned long long accR2[4][4];
    #pragma unroll
    for (int nn = 0; nn < 4; nn++)
        #pragma unroll
        for (int j = 0; j < 4; j++) { accA2[nn][j] = 0ull; accR2[nn][j] = 0ull; }

    #pragma unroll 8
    for (int k = 0; k < DIN; k += 2) {
        unsigned long long w2[4], r2[4];
        #pragma unroll
        for (int j = 0; j < 4; j++) {
            int cc = lane + 32 * j;
            w2[j] = f2u(Wsh[k * DOUT + cc], Wsh[(k + 1) * DOUT + cc]);
            r2[j] = f2u(Rsh[k * DOUT + cc], Rsh[(k + 1) * DOUT + cc]);
        }
        #pragma unroll
        for (int nn = 0; nn < 4; nn++) {
            unsigned long long a2 =
                *(const unsigned long long*)&Ash[(my + 8 * nn) * DIN + k];
            unsigned long long xv2 =
                *(const unsigned long long*)&Xsh[(my + 8 * nn) * DIN + k];
            #pragma unroll
            for (int j = 0; j < 4; j++) {
                FMA2(accA2[nn][j], w2[j], a2);
                FMA2(accR2[nn][j], r2[j], xv2);
            }
        }
    }

    // Per-column parameters at cc = lane + 32j
    float bcc[4], lwc[4], lbc[4], rbc[4];
    #pragma unroll
    for (int j = 0; j < 4; j++) {
        int cc = lane + 32 * j;
        bcc[j] = b[cc]; lwc[j] = lnw[cc]; lbc[j] = lnb[cc]; rbc[j] = rb[cc];
    }

    #pragma unroll
    for (int nn = 0; nn < 4; nn++) {
        float av[4], rv[4];
        #pragma unroll
        for (int j = 0; j < 4; j++) {
            float2 pa = u2f(accA2[nn][j]);
            float2 pr = u2f(accR2[nn][j]);
            av[j] = pa.x + pa.y + bcc[j];
            rv[j] = pr.x + pr.y + rbc[j];
        }

        float s = av[0] + av[1] + av[2] + av[3];
        float q = av[0]*av[0] + av[1]*av[1] + av[2]*av[2] + av[3]*av[3];
        #pragma unroll
        for (int o = 16; o > 0; o >>= 1) {
            s += __shfl_xor_sync(0xffffffffu, s, o);
            q += __shfl_xor_sync(0xffffffffu, q, o);
        }
        float mu  = s * (1.0f / 128.0f);
        float var = q * (1.0f / 128.0f) - mu * mu;
        float inv = rsqrtf(var + 1e-5f);

        int node = m0 + my + 8 * nn;
        if (node < N) {
            #pragma unroll
            for (int j = 0; j < 4; j++) {
                float h = (av[j] - mu) * inv * lwc[j] + lbc[j];
                float y = h + rv[j];
                out[(size_t)node * DOUT + lane + 32 * j] =
                    y * (1.0f / (1.0f + __expf(-y)));
            }
        }
    }
}

// ---------------------------------------------------------------------------
extern "C" void kernel_launch(void* const* d_in, const int* in_sizes, int n_in,
                              void* d_out, int out_size) {
    const float* x   = (const float*)d_in[0];
    const int*   ei  = (const int*)d_in[1];     // int32 OR int64 (auto-detected)
    const float* W   = (const float*)d_in[2];
    const float* b   = (const float*)d_in[3];
    const float* lnw = (const float*)d_in[4];
    const float* lnb = (const float*)d_in[5];
    const float* Rw  = (const float*)d_in[6];
    const float* rb  = (const float*)d_in[7];
    float*       out = (float*)d_out;

    const int N = in_sizes[0] / DIN;       // 50000
    const int E = in_sizes[1] / 2;         // 800000

    const size_t SMEM5 = (8192 + 8192 + 2048 + 2048) * sizeof(float); // 80 KB
    cudaFuncSetAttribute(k_fused, cudaFuncAttributeMaxDynamicSharedMemorySize,
                         (int)SMEM5);

    const int nblk = (N + 255) / 256;      // 196 scan blocks

    k_zero<<<(N + 255) / 256, 256>>>(ei, N);
    k_count<<<(E + 255) / 256, 256>>>(ei, E, N);
    k_scanA<<<nblk, 256>>>(N);
    k_scanB<<<1, 256>>>(nblk);
    k_scanC<<<(N + 255) / 256, 256>>>(N);
    k_reorder<<<(E + 255) / 256, 256>>>(ei, E, N);
    {
        int warps  = N;                       // one warp per node
        int blocks = (warps * 32 + 255) / 256;
        k_gather<<<blocks, 256>>>((const float2*)x, N);
    }
    k_fused<<<(N + 31) / 32, 256, SMEM5>>>(x, W, b, lnw, lnb, Rw, rb, out, N);
}

// round 16
// speedup vs baseline: 1.7466x; 1.0012x over previous
#include <cuda_runtime.h>
#include <math.h>
#include <string.h>

// Problem constants (shapes fixed by the dataset)
#define NN   50000
#define EE   800000
#define DIN  64
#define DOUT 128

// Scratch (no cudaMalloc allowed)
__device__ int   g_is64;
__device__ int   g_degi[NN];            // incoming-edge count (no self-loop)
__device__ int   g_start[NN];           // CSR segment start (unordered placement)
__device__ int   g_end[NN];             // CSR segment end
__device__ int   g_cursor[NN];          // fill cursors
__device__ float g_dinv[NN];
__device__ int   g_total;               // running allocation offset
__device__ int2  g_edge[EE];            // (src, __float_as_int(norm)) segmented by dst
__device__ __align__(128) float g_aggx[(size_t)NN * DIN];

// Packed f32x2 FMA: d.lo += a.lo*b.lo; d.hi += a.hi*b.hi  (2x fp32 tput)
#define FMA2(d, a, b) \
    asm("fma.rn.f32x2 %0, %1, %2, %0;" : "+l"(d) : "l"(a), "l"(b))

__device__ __forceinline__ unsigned long long f2u(float lo, float hi) {
    float2 f = make_float2(lo, hi);
    unsigned long long u;
    memcpy(&u, &f, 8);
    return u;
}
__device__ __forceinline__ float2 u2f(unsigned long long u) {
    float2 f;
    memcpy(&f, &u, 8);
    return f;
}

__device__ __forceinline__ int edge_at(const int* __restrict__ ei, int i, int is64) {
    return is64 ? (int)((const long long*)ei)[i] : ei[i];
}

// ---------------------------------------------------------------------------
// K1: zero degree histogram + total + detect edge_index dtype.
// int64 detection: upper 32-bit words of first 16 entries all zero.
__global__ void k_zero(const int* __restrict__ ei, int N) {
    int i = blockIdx.x * blockDim.x + threadIdx.x;
    if (i < N) g_degi[i] = 0;
    if (i == 0) {
        g_total = 0;
        int is64 = 1;
        #pragma unroll
        for (int k = 0; k < 16; k++)
            if (ei[2 * k + 1] != 0) is64 = 0;
        g_is64 = is64;
    }
}

// K2: degi[dst] += 1 per edge (guarded: invalid dst never counted)
__global__ void k_count(const int* __restrict__ ei, int E, int N) {
    const int is64 = g_is64;
    int e = blockIdx.x * blockDim.x + threadIdx.x;
    if (e < E) {
        int d = edge_at(ei, E + e, is64);
        if ((unsigned)d < (unsigned)N)
            atomicAdd(&g_degi[d], 1);
    }
}

// K3: allocate per-node CSR segments via atomic bump allocator (no scan).
// Placement order is arbitrary; segments are contiguous and exactly sized,
// which is all k_reorder/k_gather need. Also: cursors, dinv.
__global__ void k_offsets(int N) {
    int i = blockIdx.x * blockDim.x + threadIdx.x;
    if (i < N) {
        int deg = g_degi[i];
        int pos = atomicAdd(&g_total, deg);
        g_start[i]  = pos;
        g_end[i]    = pos + deg;
        g_cursor[i] = 0;
        g_dinv[i]   = rsqrtf((float)(deg + 1));
    }
}

// K4: reorder edges into CSR-by-dst with packed (src, norm).
// Invariant: every edge counted in k_count gets exactly one slot written
// (invalid src -> norm 0), so gather never reads garbage.
__global__ void k_reorder(const int* __restrict__ ei, int E, int N) {
    const int is64 = g_is64;
    int e = blockIdx.x * blockDim.x + threadIdx.x;
    if (e >= E) return;
    int d = edge_at(ei, E + e, is64);
    if ((unsigned)d >= (unsigned)N) return;            // never counted -> skip
    int s = edge_at(ei, e, is64);
    float nrm = 0.0f;
    if ((unsigned)s < (unsigned)N) {
        nrm = g_dinv[s] * g_dinv[d];
    } else {
        s = 0;                                         // slot written, contributes 0
    }
    int pos = g_start[d] + atomicAdd(&g_cursor[d], 1);
    g_edge[pos] = make_int2(s, __float_as_int(nrm));
}

// K5: gather  aggx[n] = x[n]*dinv[n]^2 + sum_{e: dst=e} x[src_e]*norm_e
// One warp per node; lane holds float2 (2 of 64 columns). No atomics.
__global__ void k_gather(const float2* __restrict__ x2, int N) {
    int w = (blockIdx.x * blockDim.x + threadIdx.x) >> 5;
    if (w >= N) return;
    int lane = threadIdx.x & 31;

    float di = g_dinv[w];
    float sc = di * di;
    float2 acc = x2[(size_t)w * 32 + lane];
    acc.x *= sc; acc.y *= sc;

    int i   = g_start[w];
    int end = g_end[w];
    for (; i + 1 < end; i += 2) {                      // 2-edge unroll (MLP)
        int2 e0 = g_edge[i];
        int2 e1 = g_edge[i + 1];
        float n0 = __int_as_float(e0.y);
        float n1 = __int_as_float(e1.y);
        float2 v0 = x2[(size_t)e0.x * 32 + lane];
        float2 v1 = x2[(size_t)e1.x * 32 + lane];
        acc.x += v0.x * n0 + v1.x * n1;
        acc.y += v0.y * n0 + v1.y * n1;
    }
    if (i < end) {
        int2 e0 = g_edge[i];
        float n0 = __int_as_float(e0.y);
        float2 v0 = x2[(size_t)e0.x * 32 + lane];
        acc.x += v0.x * n0;
        acc.y += v0.y * n0;
    }
    ((float2*)g_aggx)[(size_t)w * 32 + lane] = acc;
}

// ---------------------------------------------------------------------------
// K6: fused  out = SiLU( LN(aggx@W + b)*ln_w + ln_b + x@res_W + res_b )
// Block = 256 threads = 8 warps, 32-node tile. Inner loop uses packed
// fma.rn.f32x2 pairing over the K dimension: accumulator lanes hold
// (sum over even k, sum over odd k); halves added in the epilogue.
// Thread layout: warp my owns nodes my+8nn; lane owns cols lane+32j (j=0..3).
__global__ void k_fused(const float* __restrict__ x,
                        const float* __restrict__ W,
                        const float* __restrict__ b,
                        const float* __restrict__ lnw,
                        const float* __restrict__ lnb,
                        const float* __restrict__ Rw,
                        const float* __restrict__ rb,
                        float* __restrict__ out, int N) {
    extern __shared__ float sh[];
    float* Wsh = sh;                 // 64*128 = 8192 floats
    float* Rsh = sh + 8192;          // 8192
    float* Ash = sh + 16384;         // 32*64 = 2048
    float* Xsh = sh + 18432;         // 2048

    const int tid = threadIdx.x;
    const int m0  = blockIdx.x * 32;

    // Stage weights (2048 float4 each)
    {
        float4* Wd = (float4*)Wsh; const float4* Wg = (const float4*)W;
        float4* Rd = (float4*)Rsh; const float4* Rg = (const float4*)Rw;
        #pragma unroll
        for (int i = 0; i < 8; i++) {
            Wd[tid + i * 256] = Wg[tid + i * 256];
            Rd[tid + i * 256] = Rg[tid + i * 256];
        }
    }
    // Stage node tiles: 512 float4 each (2 per thread)
    {
        float4* Ad = (float4*)Ash; const float4* Ag = (const float4*)g_aggx;
        float4* Xd = (float4*)Xsh; const float4* Xg = (const float4*)x;
        #pragma unroll
        for (int i = 0; i < 2; i++) {
            int idx  = tid + i * 256;          // 0..511
            int node = m0 + (idx >> 4);
            int c    = idx & 15;
            float4 av = make_float4(0.f, 0.f, 0.f, 0.f);
            float4 xv = make_float4(0.f, 0.f, 0.f, 0.f);
            if (node < N) {
                av = Ag[(size_t)node * 16 + c];
                xv = Xg[(size_t)node * 16 + c];
            }
            Ad[idx] = av;
            Xd[idx] = xv;
        }
    }
    __syncthreads();

    const int my   = tid >> 5;   // warp id 0..7 -> nodes my, my+8, my+16, my+24
    const int lane = tid & 31;   // lane -> cols lane, lane+32, lane+64, lane+96

    unsigned long long accA2[4][4];   // [node][colgroup] packed (even-k, odd-k)
    unsigned long long accR2[4][4];
    #pragma unroll
    for (int nn = 0; nn < 4; nn++)
        #pragma unroll
        for (int j = 0; j < 4; j++) { accA2[nn][j] = 0ull; accR2[nn][j] = 0ull; }

    #pragma unroll 8
    for (int k = 0; k < DIN; k += 2) {
        unsigned long long w2[4], r2[4];
        #pragma unroll
        for (int j = 0; j < 4; j++) {
            int cc = lane + 32 * j;
            w2[j] = f2u(Wsh[k * DOUT + cc], Wsh[(k + 1) * DOUT + cc]);
            r2[j] = f2u(Rsh[k * DOUT + cc], Rsh[(k + 1) * DOUT + cc]);
        }
        #pragma unroll
        for (int nn = 0; nn < 4; nn++) {
            unsigned long long a2 =
                *(const unsigned long long*)&Ash[(my + 8 * nn) * DIN + k];
            unsigned long long xv2 =
                *(const unsigned long long*)&Xsh[(my + 8 * nn) * DIN + k];
            #pragma unroll
            for (int j = 0; j < 4; j++) {
                FMA2(accA2[nn][j], w2[j], a2);
                FMA2(accR2[nn][j], r2[j], xv2);
            }
        }
    }

    // Per-column parameters at cc = lane + 32j
    float bcc[4], lwc[4], lbc[4], rbc[4];
    #pragma unroll
    for (int j = 0; j < 4; j++) {
        int cc = lane + 32 * j;
        bcc[j] = b[cc]; lwc[j] = lnw[cc]; lbc[j] = lnb[cc]; rbc[j] = rb[cc];
    }

    #pragma unroll
    for (int nn = 0; nn < 4; nn++) {
        float av[4], rv[4];
        #pragma unroll
        for (int j = 0; j < 4; j++) {
            float2 pa = u2f(accA2[nn][j]);
            float2 pr = u2f(accR2[nn][j]);
            av[j] = pa.x + pa.y + bcc[j];
            rv[j] = pr.x + pr.y + rbc[j];
        }

        float s = av[0] + av[1] + av[2] + av[3];
        float q = av[0]*av[0] + av[1]*av[1] + av[2]*av[2] + av[3]*av[3];
        #pragma unroll
        for (int o = 16; o > 0; o >>= 1) {
            s += __shfl_xor_sync(0xffffffffu, s, o);
            q += __shfl_xor_sync(0xffffffffu, q, o);
        }
        float mu  = s * (1.0f / 128.0f);
        float var = q * (1.0f / 128.0f) - mu * mu;
        float inv = rsqrtf(var + 1e-5f);

        int node = m0 + my + 8 * nn;
        if (node < N) {
            #pragma unroll
            for (int j = 0; j < 4; j++) {
                float h = (av[j] - mu) * inv * lwc[j] + lbc[j];
                float y = h + rv[j];
                out[(size_t)node * DOUT + lane + 32 * j] =
                    y * (1.0f / (1.0f + __expf(-y)));
            }
        }
    }
}

// ---------------------------------------------------------------------------
extern "C" void kernel_launch(void* const* d_in, const int* in_sizes, int n_in,
                              void* d_out, int out_size) {
    const float* x   = (const float*)d_in[0];
    const int*   ei  = (const int*)d_in[1];     // int32 OR int64 (auto-detected)
    const float* W   = (const float*)d_in[2];
    const float* b   = (const float*)d_in[3];
    const float* lnw = (const float*)d_in[4];
    const float* lnb = (const float*)d_in[5];
    const float* Rw  = (const float*)d_in[6];
    const float* rb  = (const float*)d_in[7];
    float*       out = (float*)d_out;

    const int N = in_sizes[0] / DIN;       // 50000
    const int E = in_sizes[1] / 2;         // 800000

    const size_t SMEM5 = (8192 + 8192 + 2048 + 2048) * sizeof(float); // 80 KB
    cudaFuncSetAttribute(k_fused, cudaFuncAttributeMaxDynamicSharedMemorySize,
                         (int)SMEM5);

    k_zero<<<(N + 255) / 256, 256>>>(ei, N);
    k_count<<<(E + 255) / 256, 256>>>(ei, E, N);
    k_offsets<<<(N + 255) / 256, 256>>>(N);
    k_reorder<<<(E + 255) / 256, 256>>>(ei, E, N);
    {
        int warps  = N;                       // one warp per node
        int blocks = (warps * 32 + 255) / 256;
        k_gather<<<blocks, 256>>>((const float2*)x, N);
    }
    k_fused<<<(N + 31) / 32, 256, SMEM5>>>(x, W, b, lnw, lnb, Rw, rb, out, N);
}